// round 2
// baseline (speedup 1.0000x reference)
#include <cuda_runtime.h>

typedef unsigned long long ull;

#define BATCH  4096
#define TSTEPS 1024
#define EMD    128
#define CELL   128
#define G4     512
#define KTOT   256
#define DOUT   5
#define NCTA   128
#define ROWS   32
#define NTHR   256
#define ASTRIDE 33
#define TILEK  16
#define NTILES 16
#define WBUF_FLOATS (TILEK * G4)   /* 8192 */

#define HOFF ((size_t)BATCH * TSTEPS * DOUT)
#define COFF (HOFF + (size_t)BATCH * CELL)

// ---- shared memory layout (float offsets) ----
#define OFF_W    0                              /* 2 x 8192 = 16384 */
#define OFF_A    16384                          /* 256*33 = 8448    */
#define OFF_GACT (OFF_A + KTOT * ASTRIDE)       /* 24832, 512*32    */
#define OFF_B    (OFF_GACT + G4 * ROWS)         /* 41216, 512       */
#define OFF_WE2  (OFF_B + G4)                   /* 41728, 256       */
#define OFF_BE   (OFF_WE2 + 256)                /* 41984, 128       */
#define OFF_WO   (OFF_BE + 128)                 /* 42112, 5*129->648*/
#define OFF_BO   (OFF_WO + 648)                 /* 42760, 8         */
#define SMEM_FLOATS (OFF_BO + 8)                /* 42768            */
#define SMEM_BYTES  (SMEM_FLOATS * 4)           /* 171072           */

// ---- scratch (static device arrays; no allocation) ----
__device__ float g_Wt[KTOT * G4];   // [k][gate] combined transposed weights
__device__ float g_b[G4];           // b_ih + b_hh

// ---- helpers ----
__device__ __forceinline__ unsigned smem_u32(const void* p) {
    return (unsigned)__cvta_generic_to_shared(p);
}
__device__ __forceinline__ ull ffma2(ull a, ull b, ull c) {
    ull d;
    asm("fma.rn.f32x2 %0, %1, %2, %3;" : "=l"(d) : "l"(a), "l"(b), "l"(c));
    return d;
}
__device__ __forceinline__ ull pack_dup(float v) {
    ull r;
    asm("mov.b64 %0, {%1, %1};" : "=l"(r) : "f"(v));
    return r;
}
__device__ __forceinline__ float2 unpack2(ull v) {
    float2 r;
    asm("mov.b64 {%0, %1}, %2;" : "=f"(r.x), "=f"(r.y) : "l"(v));
    return r;
}
__device__ __forceinline__ float sig_(float x) {
    return __fdividef(1.f, 1.f + __expf(-x));
}
__device__ __forceinline__ float tanh_(float x) {
    return fmaf(2.f, sig_(x + x), -1.f);
}

#define CP_ASYNC16(dst, src) asm volatile("cp.async.cg.shared.global [%0], [%1], 16;" :: "r"(dst), "l"(src))
#define CP_COMMIT()          asm volatile("cp.async.commit_group;")
#define CP_WAIT0()           asm volatile("cp.async.wait_group 0;")

// ---- prep: fuse W_ih|W_hh into [k][g] transposed layout, fold biases ----
__global__ void prep_weights(const float* __restrict__ W_ih, const float* __restrict__ W_hh,
                             const float* __restrict__ b_ih, const float* __restrict__ b_hh) {
    int idx = blockIdx.x * blockDim.x + threadIdx.x;
    if (idx < KTOT * G4) {
        int k = idx >> 9, g = idx & 511;
        g_Wt[idx] = (k < EMD) ? W_ih[g * EMD + k] : W_hh[g * CELL + (k - EMD)];
    }
    if (idx < G4) g_b[idx] = b_ih[idx] + b_hh[idx];
}

// ---- persistent LSTM: CTA = 32 batch rows for all T steps ----
__global__ void __launch_bounds__(NTHR, 1) lstm_main(
    const float* __restrict__ x,
    const float* __restrict__ We, const float* __restrict__ be,
    const float* __restrict__ Wo, const float* __restrict__ bo,
    float* __restrict__ out)
{
    extern __shared__ float sm[];
    const int tid  = threadIdx.x;
    const int lane = tid & 31;
    const int w    = tid >> 5;
    const int rowbase = blockIdx.x * ROWS;

    // prologue: stage parameters, zero A (h half must be 0 at t=0)
    for (int i = tid; i < G4; i += NTHR)        sm[OFF_B + i]   = g_b[i];
    for (int i = tid; i < 2 * EMD; i += NTHR)   sm[OFF_WE2 + i] = We[i];
    for (int i = tid; i < EMD; i += NTHR)       sm[OFF_BE + i]  = be[i];
    for (int i = tid; i < DOUT * CELL; i += NTHR)
        sm[OFF_WO + (i >> 7) * 129 + (i & 127)] = Wo[i];
    if (tid < 8) sm[OFF_BO + tid] = (tid < DOUT) ? bo[tid] : 0.f;
    for (int i = tid; i < KTOT * ASTRIDE; i += NTHR) sm[OFF_A + i] = 0.f;

    float creg[16];
    #pragma unroll
    for (int m = 0; m < 16; ++m) creg[m] = 0.f;

    const int j0    = w << 4;       // cell slice for embed/combine
    const int gtype = w >> 1;       // 0,1:i,f(sig)  2:g(tanh)  3:o(sig)
    const ull* sBull = (const ull*)(sm + OFF_B);
    const float2* sWe2 = (const float2*)(sm + OFF_WE2);

    __syncthreads();

    for (int t = 0; t < TSTEPS; ++t) {
        // ---- embed MLP: e = relu(x @ We^T + be), write into A[0..127][row] ----
        const float2 xv = ((const float2*)x)[(size_t)(rowbase + lane) * TSTEPS + t];
        #pragma unroll
        for (int m = 0; m < 16; ++m) {
            int j = j0 + m;
            float2 wv = sWe2[j];
            float e = fmaf(xv.x, wv.x, fmaf(xv.y, wv.y, sm[OFF_BE + j]));
            sm[OFF_A + j * ASTRIDE + lane] = fmaxf(e, 0.f);
        }

        // ---- gate GEMM: acc[row=lane][gates 64w..64w+63] with packed f32x2 ----
        ull acc[32];
        #pragma unroll
        for (int c = 0; c < 32; ++c) acc[c] = sBull[(w << 5) + c];  // bias preload

        // prefetch weight tile 0
        {
            const float* src = g_Wt + (tid << 2);
            unsigned dst = smem_u32(sm + OFF_W) + (tid << 4);
            #pragma unroll
            for (int m2 = 0; m2 < 8; ++m2)
                CP_ASYNC16(dst + m2 * 4096, src + m2 * 1024);
            CP_COMMIT();
        }

        #pragma unroll 1
        for (int ti = 0; ti < NTILES; ++ti) {
            CP_WAIT0();
            __syncthreads();
            if (ti + 1 < NTILES) {
                const float* src = g_Wt + (ti + 1) * WBUF_FLOATS + (tid << 2);
                unsigned dst = smem_u32(sm + OFF_W + ((ti + 1) & 1) * WBUF_FLOATS) + (tid << 4);
                #pragma unroll
                for (int m2 = 0; m2 < 8; ++m2)
                    CP_ASYNC16(dst + m2 * 4096, src + m2 * 1024);
                CP_COMMIT();
            }
            const float* wb   = sm + OFF_W + (ti & 1) * WBUF_FLOATS + (w << 6);
            const float* arow = sm + OFF_A + ti * TILEK * ASTRIDE + lane;
            #pragma unroll
            for (int kk = 0; kk < TILEK; ++kk) {
                ull ap = pack_dup(arow[kk * ASTRIDE]);            // (a,a)
                const ulonglong2* wr = (const ulonglong2*)(wb + kk * G4);
                #pragma unroll
                for (int q = 0; q < 16; ++q) {
                    ulonglong2 wv = wr[q];                         // broadcast LDS.128
                    acc[2 * q]     = ffma2(ap, wv.x, acc[2 * q]);
                    acc[2 * q + 1] = ffma2(ap, wv.y, acc[2 * q + 1]);
                }
            }
        }

        // ---- activations (warp-uniform gate type), stage to gact[g][row] ----
        #pragma unroll
        for (int c = 0; c < 32; ++c) {
            float2 v = unpack2(acc[c]);
            int g = (w << 6) + (c << 1);
            if (gtype == 2) { v.x = tanh_(v.x); v.y = tanh_(v.y); }
            else            { v.x = sig_(v.x);  v.y = sig_(v.y);  }
            sm[OFF_GACT + g * ROWS + lane]       = v.x;
            sm[OFF_GACT + (g + 1) * ROWS + lane] = v.y;
        }
        __syncthreads();

        // ---- combine: c' = f*c + i*g ; h' = o*tanh(c') ; h' -> A[128+j][row] ----
        const bool last = (t == TSTEPS - 1);
        #pragma unroll
        for (int m = 0; m < 16; ++m) {
            int j = j0 + m;
            float iv = sm[OFF_GACT + j * ROWS + lane];
            float fv = sm[OFF_GACT + (EMD + j) * ROWS + lane];
            float gv = sm[OFF_GACT + (2 * EMD + j) * ROWS + lane];
            float ov = sm[OFF_GACT + (3 * EMD + j) * ROWS + lane];
            float cn = fmaf(fv, creg[m], iv * gv);
            creg[m] = cn;
            float hn = ov * tanh_(cn);
            sm[OFF_A + (EMD + j) * ASTRIDE + lane] = hn;
            if (last) {
                out[HOFF + (size_t)(rowbase + lane) * CELL + j] = hn;
                out[COFF + (size_t)(rowbase + lane) * CELL + j] = cn;
            }
        }
        __syncthreads();

        // ---- output projection: y = h' @ Wo^T + bo (160 threads) ----
        if (tid < ROWS * DOUT) {
            int r = tid / DOUT, d = tid - r * DOUT;
            float s = sm[OFF_BO + d];
            const float* wrow = sm + OFF_WO + d * 129;
            const float* hcol = sm + OFF_A + EMD * ASTRIDE + r;   // stride-33 column: conflict-free
            #pragma unroll 8
            for (int j = 0; j < CELL; ++j)
                s = fmaf(hcol[j * ASTRIDE], wrow[j], s);
            out[((size_t)(rowbase + r) * TSTEPS + t) * DOUT + d] = s;
        }
        // no barrier needed: next embed writes A[0..127][*], disjoint from y reads of A[128..255][*];
        // next GEMM reads occur only after the ti=0 __syncthreads.
    }
}

extern "C" void kernel_launch(void* const* d_in, const int* in_sizes, int n_in,
                              void* d_out, int out_size) {
    const float* x    = (const float*)d_in[0];
    const float* We   = (const float*)d_in[1];
    const float* be   = (const float*)d_in[2];
    const float* W_ih = (const float*)d_in[3];
    const float* W_hh = (const float*)d_in[4];
    const float* b_ih = (const float*)d_in[5];
    const float* b_hh = (const float*)d_in[6];
    const float* Wo   = (const float*)d_in[7];
    const float* bo   = (const float*)d_in[8];
    float* out = (float*)d_out;

    cudaFuncSetAttribute(lstm_main, cudaFuncAttributeMaxDynamicSharedMemorySize, SMEM_BYTES);

    prep_weights<<<512, 256>>>(W_ih, W_hh, b_ih, b_hh);
    lstm_main<<<NCTA, NTHR, SMEM_BYTES>>>(x, We, be, Wo, bo, out);
}

// round 3
// speedup vs baseline: 1.3062x; 1.3062x over previous
#include <cuda_runtime.h>

typedef unsigned long long ull;

#define BATCH  4096
#define TSTEPS 1024
#define EMD    128
#define CELL   128
#define G4     512
#define KTOT   256
#define DOUT   5
#define NCTA   128
#define ROWS   32
#define NTHR   512
#define TILEK  16
#define NTILES 16
#define WBUF   (TILEK * G4)     /* 8192 floats per buffer */
#define A2S    34               /* A2 stride per k, in float2 (ull) units = 272B */
#define GST    516              /* GACT row stride in floats = 2064B */

#define HOFF ((size_t)BATCH * TSTEPS * DOUT)
#define COFF (HOFF + (size_t)BATCH * CELL)

// ---- shared memory layout (float offsets) ----
#define OFF_W    0                              /* 2 x 8192 = 16384            */
#define OFF_A2   (2 * WBUF)                     /* 16384; 256*34 ull = 17408 f */
#define OFF_GACT (OFF_A2 + KTOT * A2S * 2)      /* 33792; 32*516 = 16512       */
#define OFF_B    (OFF_GACT + ROWS * GST)        /* 50304; 512                  */
#define OFF_WE2  (OFF_B + G4)                   /* 50816; 256                  */
#define OFF_BE   (OFF_WE2 + 256)                /* 51072; 128                  */
#define OFF_WO   (OFF_BE + 128)                 /* 51200; 5*132 = 660          */
#define OFF_BO   (OFF_WO + DOUT * 132)          /* 51860; 12 (pad)             */
#define OFF_XB   (OFF_BO + 12)                  /* 51872 (8B aligned); 64      */
#define SMEM_FLOATS (OFF_XB + 64)               /* 51936                       */
#define SMEM_BYTES  (SMEM_FLOATS * 4)           /* 207744                      */

// ---- scratch (static device arrays; allocation-free) ----
__device__ float g_Wt[KTOT * G4];   // [k][gate] combined transposed weights
__device__ float g_b[G4];           // b_ih + b_hh

// ---- helpers ----
__device__ __forceinline__ unsigned smem_u32(const void* p) {
    return (unsigned)__cvta_generic_to_shared(p);
}
__device__ __forceinline__ ull ffma2(ull a, ull b, ull c) {
    ull d;
    asm("fma.rn.f32x2 %0, %1, %2, %3;" : "=l"(d) : "l"(a), "l"(b), "l"(c));
    return d;
}
__device__ __forceinline__ ull pack2(float x, float y) {
    ull r;
    asm("mov.b64 %0, {%1, %2};" : "=l"(r) : "f"(x), "f"(y));
    return r;
}
__device__ __forceinline__ float2 unpack2(ull v) {
    float2 r;
    asm("mov.b64 {%0, %1}, %2;" : "=f"(r.x), "=f"(r.y) : "l"(v));
    return r;
}
__device__ __forceinline__ float sig_(float x) {
    return __fdividef(1.f, 1.f + __expf(-x));
}
__device__ __forceinline__ float tanh_(float x) {
    return fmaf(2.f, sig_(x + x), -1.f);
}

#define CP_ASYNC16(dst, src) asm volatile("cp.async.cg.shared.global [%0], [%1], 16;" :: "r"(dst), "l"(src))
#define CP_COMMIT()          asm volatile("cp.async.commit_group;")
#define CP_WAIT0()           asm volatile("cp.async.wait_group 0;")

// ---- prep: fuse W_ih|W_hh into [k][g] transposed layout, fold biases ----
__global__ void prep_weights(const float* __restrict__ W_ih, const float* __restrict__ W_hh,
                             const float* __restrict__ b_ih, const float* __restrict__ b_hh) {
    int idx = blockIdx.x * blockDim.x + threadIdx.x;
    if (idx < KTOT * G4) {
        int k = idx >> 9, g = idx & 511;
        g_Wt[idx] = (k < EMD) ? W_ih[g * EMD + k] : W_hh[g * CELL + (k - EMD)];
    }
    if (idx < G4) g_b[idx] = b_ih[idx] + b_hh[idx];
}

// ---- persistent LSTM: CTA = 32 batch rows for all T steps ----
__global__ void __launch_bounds__(NTHR, 1) lstm_main(
    const float* __restrict__ x,
    const float* __restrict__ We, const float* __restrict__ be,
    const float* __restrict__ Wo, const float* __restrict__ bo,
    float* __restrict__ out)
{
    extern __shared__ float sm[];
    const int tid     = threadIdx.x;
    const int rowbase = blockIdx.x * ROWS;

    // GEMM thread map: 4 rows x 8 cols per thread
    const int rg = tid >> 6;                 // 0..7  -> rows 4rg..4rg+3
    const int cg = tid & 63;                 // 0..63 -> cols {4cg..+3, 256+4cg..+3}
    const bool set1_tanh = (cg < 32);        // warp-uniform: set1 is g-gate iff cg<32

    // epilogue thread map: cell j x 8 rows
    const int j  = tid >> 2;                 // 0..127
    const int rb = tid & 3;                  // rows rb + 4m
    // output-projection map
    const int yr = tid / DOUT, yd = tid - yr * DOUT;   // valid when tid < 160

    ull* const A2u = (ull*)(sm + OFF_A2);
    const float2* const sWe2 = (const float2*)(sm + OFF_WE2);
    const float2* const xb   = (const float2*)(sm + OFF_XB);

    // prologue: stage parameters, zero A2 (h half must be 0 at t=0)
    for (int i = tid; i < G4; i += NTHR)      sm[OFF_B + i]   = g_b[i];
    for (int i = tid; i < 2 * EMD; i += NTHR) sm[OFF_WE2 + i] = We[i];
    for (int i = tid; i < EMD; i += NTHR)     sm[OFF_BE + i]  = be[i];
    for (int i = tid; i < DOUT * CELL; i += NTHR)
        sm[OFF_WO + (i >> 7) * 132 + (i & 127)] = Wo[i];
    if (tid < 12) sm[OFF_BO + tid] = (tid < DOUT) ? bo[tid] : 0.f;
    for (int i = tid; i < KTOT * A2S * 2; i += NTHR) sm[OFF_A2 + i] = 0.f;

    float creg[8];
    #pragma unroll
    for (int m = 0; m < 8; ++m) creg[m] = 0.f;

    // prefetch weight tile 0 into buf0
    {
        const float* src = g_Wt + (tid << 2);
        unsigned dst = smem_u32(sm + OFF_W) + (tid << 4);
        #pragma unroll
        for (int m2 = 0; m2 < 4; ++m2)
            CP_ASYNC16(dst + m2 * 8192, src + m2 * 2048);
        CP_COMMIT();
    }
    __syncthreads();

    for (int t = 0; t < TSTEPS; ++t) {
        // ---- (A) stage x[rows][t] into smem ----
        if (tid < ROWS)
            ((float2*)(sm + OFF_XB))[tid] =
                ((const float2*)x)[(size_t)(rowbase + tid) * TSTEPS + t];
        __syncthreads();

        // ---- (C) embed MLP: e = relu(x @ We^T + be) -> A2[j][row] duplicated ----
        {
            float2 wej = sWe2[j];
            float  bej = sm[OFF_BE + j];
            #pragma unroll
            for (int m = 0; m < 8; ++m) {
                int row = rb + 4 * m;
                float2 xv = xb[row];
                float e = fmaf(xv.x, wej.x, fmaf(xv.y, wej.y, bej));
                e = fmaxf(e, 0.f);
                A2u[j * A2S + row] = pack2(e, e);
            }
        }

        // ---- (E) gate GEMM: acc[4 rows][8 cols] with packed f32x2 ----
        ull acc[16];
        {
            const ulonglong2* b2 = (const ulonglong2*)(sm + OFF_B);
            ulonglong2 b0 = b2[cg], b1 = b2[cg + 64];
            #pragma unroll
            for (int r = 0; r < 4; ++r) {
                acc[r * 4 + 0] = b0.x; acc[r * 4 + 1] = b0.y;
                acc[r * 4 + 2] = b1.x; acc[r * 4 + 3] = b1.y;
            }
        }

        #pragma unroll 1
        for (int ti = 0; ti < NTILES; ++ti) {
            CP_WAIT0();
            __syncthreads();
            {   // prefetch next tile (tile 0 of next step when ti==15)
                int nti = (ti + 1) & 15;
                if (ti < 15 || t + 1 < TSTEPS) {
                    const float* src = g_Wt + nti * WBUF + (tid << 2);
                    unsigned dst = smem_u32(sm + OFF_W + ((ti + 1) & 1) * WBUF) + (tid << 4);
                    #pragma unroll
                    for (int m2 = 0; m2 < 4; ++m2)
                        CP_ASYNC16(dst + m2 * 8192, src + m2 * 2048);
                    CP_COMMIT();
                }
            }
            const float* wb = sm + OFF_W + (ti & 1) * WBUF + (cg << 2);
            const ull*   ab = A2u + ti * TILEK * A2S + (rg << 2);
            #pragma unroll
            for (int kk = 0; kk < TILEK; ++kk) {
                ull a0 = ab[kk * A2S + 0];
                ull a1 = ab[kk * A2S + 1];
                ull a2 = ab[kk * A2S + 2];
                ull a3 = ab[kk * A2S + 3];
                ulonglong2 wl = *(const ulonglong2*)(wb + kk * G4);
                ulonglong2 wh = *(const ulonglong2*)(wb + kk * G4 + 256);
                acc[0]  = ffma2(a0, wl.x, acc[0]);  acc[1]  = ffma2(a0, wl.y, acc[1]);
                acc[2]  = ffma2(a0, wh.x, acc[2]);  acc[3]  = ffma2(a0, wh.y, acc[3]);
                acc[4]  = ffma2(a1, wl.x, acc[4]);  acc[5]  = ffma2(a1, wl.y, acc[5]);
                acc[6]  = ffma2(a1, wh.x, acc[6]);  acc[7]  = ffma2(a1, wh.y, acc[7]);
                acc[8]  = ffma2(a2, wl.x, acc[8]);  acc[9]  = ffma2(a2, wl.y, acc[9]);
                acc[10] = ffma2(a2, wh.x, acc[10]); acc[11] = ffma2(a2, wh.y, acc[11]);
                acc[12] = ffma2(a3, wl.x, acc[12]); acc[13] = ffma2(a3, wl.y, acc[13]);
                acc[14] = ffma2(a3, wh.x, acc[14]); acc[15] = ffma2(a3, wh.y, acc[15]);
            }
        }

        // ---- (F) activations -> GACT[row][g] (STS.128, conflict-free) ----
        #pragma unroll
        for (int r = 0; r < 4; ++r) {
            float2 v0 = unpack2(acc[r * 4 + 0]);
            float2 v1 = unpack2(acc[r * 4 + 1]);
            float2 v2 = unpack2(acc[r * 4 + 2]);
            float2 v3 = unpack2(acc[r * 4 + 3]);
            v0.x = sig_(v0.x); v0.y = sig_(v0.y);
            v1.x = sig_(v1.x); v1.y = sig_(v1.y);
            if (set1_tanh) { v2.x = tanh_(v2.x); v2.y = tanh_(v2.y);
                             v3.x = tanh_(v3.x); v3.y = tanh_(v3.y); }
            else           { v2.x = sig_(v2.x);  v2.y = sig_(v2.y);
                             v3.x = sig_(v3.x);  v3.y = sig_(v3.y); }
            float* gr = sm + OFF_GACT + (4 * rg + r) * GST + (cg << 2);
            ulonglong2 s0; s0.x = pack2(v0.x, v0.y); s0.y = pack2(v1.x, v1.y);
            ulonglong2 s1; s1.x = pack2(v2.x, v2.y); s1.y = pack2(v3.x, v3.y);
            *(ulonglong2*)gr         = s0;
            *(ulonglong2*)(gr + 256) = s1;
        }
        __syncthreads();

        // ---- (G) combine: c' = f*c + i*g ; h' = o*tanh(c') -> A2 h half ----
        const bool last = (t == TSTEPS - 1);
        #pragma unroll
        for (int m = 0; m < 8; ++m) {
            int row = rb + 4 * m;
            const float* gr = sm + OFF_GACT + row * GST + j;
            float iv = gr[0], fv = gr[EMD], gv = gr[2 * EMD], ov = gr[3 * EMD];
            float cn = fmaf(fv, creg[m], iv * gv);
            creg[m] = cn;
            float hn = ov * tanh_(cn);
            A2u[(EMD + j) * A2S + row] = pack2(hn, hn);
            if (last) {
                out[HOFF + (size_t)(rowbase + row) * CELL + j] = hn;
                out[COFF + (size_t)(rowbase + row) * CELL + j] = cn;
            }
        }
        __syncthreads();

        // ---- (H) output projection: y = h' @ Wo^T + bo ----
        if (tid < ROWS * DOUT) {
            float s0 = sm[OFF_BO + yd], s1 = 0.f, s2 = 0.f, s3 = 0.f;
            const float* wr_ = sm + OFF_WO + yd * 132;
            const float* hp  = sm + OFF_A2 + EMD * A2S * 2 + yr * 2;  // low float of dup
            #pragma unroll 8
            for (int jj = 0; jj < CELL; jj += 4) {
                s0 = fmaf(hp[(jj + 0) * (A2S * 2)], wr_[jj + 0], s0);
                s1 = fmaf(hp[(jj + 1) * (A2S * 2)], wr_[jj + 1], s1);
                s2 = fmaf(hp[(jj + 2) * (A2S * 2)], wr_[jj + 2], s2);
                s3 = fmaf(hp[(jj + 3) * (A2S * 2)], wr_[jj + 3], s3);
            }
            out[((size_t)(rowbase + yr) * TSTEPS + t) * DOUT + yd] = (s0 + s1) + (s2 + s3);
        }
        // next step's (A)+(B) barrier orders xbuf rewrite; A2 e-writes are
        // disjoint from y-proj h-reads; GEMM reads gated by tile-0 barrier.
    }
    CP_WAIT0();   // drain any in-flight prefetch before exit
}

extern "C" void kernel_launch(void* const* d_in, const int* in_sizes, int n_in,
                              void* d_out, int out_size) {
    const float* x    = (const float*)d_in[0];
    const float* We   = (const float*)d_in[1];
    const float* be   = (const float*)d_in[2];
    const float* W_ih = (const float*)d_in[3];
    const float* W_hh = (const float*)d_in[4];
    const float* b_ih = (const float*)d_in[5];
    const float* b_hh = (const float*)d_in[6];
    const float* Wo   = (const float*)d_in[7];
    const float* bo   = (const float*)d_in[8];
    float* out = (float*)d_out;

    cudaFuncSetAttribute(lstm_main, cudaFuncAttributeMaxDynamicSharedMemorySize, SMEM_BYTES);

    prep_weights<<<512, 256>>>(W_ih, W_hh, b_ih, b_hh);
    lstm_main<<<NCTA, NTHR, SMEM_BYTES>>>(x, We, be, Wo, bo, out);
}